// round 1
// baseline (speedup 1.0000x reference)
#include <cuda_runtime.h>
#include <math.h>

#define T_LEN 32768
#define AD 512
#define CCH 32
#define KF 31
#define DU 1024
#define EP 512
#define NBRED 128

// ---------------- scratch (device globals; no allocation) ----------------
__device__ float g_conv[CCH * T_LEN];     // [c][t]  4MB
__device__ float g_dz[AD];
__device__ float g_e[T_LEN];
__device__ float g_q[T_LEN];
__device__ float g_p[T_LEN];
__device__ float g_emax;
__device__ float g_partS[NBRED];
__device__ float g_part2[NBRED];
__device__ float g_cpart[NBRED * EP];

__device__ __forceinline__ float tanh_f(float x) {
    // tanh(x) = 1 - 2/(exp(2x)+1); __expf -> MUFU.EX2 (~2^-22), robust at +/-inf
    float e = __expf(2.0f * x);
    return 1.0f - __fdividef(2.0f, e + 1.0f);
}

// ---------------- k_dz: dz[a] = sum_k W_dec[a,k] * dec_z[k] ----------------
__global__ void k_dz(const float* __restrict__ dec_z, const float* __restrict__ W_dec) {
    int warp = (blockIdx.x * blockDim.x + threadIdx.x) >> 5;
    int lane = threadIdx.x & 31;
    if (warp >= AD) return;
    const float* row = W_dec + warp * DU;
    float acc = 0.f;
    #pragma unroll 4
    for (int k = lane; k < DU; k += 32) acc += row[k] * dec_z[k];
    #pragma unroll
    for (int o = 16; o; o >>= 1) acc += __shfl_xor_sync(0xffffffffu, acc, o);
    if (lane == 0) g_dz[warp] = acc;
}

// ---------------- k_conv: g_conv[c][t] = conv1d(att_prev)[c,t] + b[c] ------
__global__ void k_conv(const float* __restrict__ ap, const float* __restrict__ cw,
                       const float* __restrict__ cb) {
    int b = blockIdx.x;
    int c = b >> 7;                       // 32 channels, 128 t-blocks each
    int t = ((b & 127) << 8) + threadIdx.x;
    float acc = cb[c];
    const float* w = cw + c * KF;
    #pragma unroll
    for (int f = 0; f < KF; f++) {
        int idx = t - 15 + f;
        float a = (idx >= 0 && idx < T_LEN) ? __ldg(ap + idx) : 0.f;
        acc += a * __ldg(w + f);
    }
    g_conv[c * T_LEN + t] = acc;
}

// ---------------- k_e: fused proj-GEMM + tanh + W_g dot -> e[t] ------------
// block: 64 t x 512 a (4 chunks of 128a), 256 threads, thread tile 8t x 4a.
__global__ __launch_bounds__(256, 3) void k_e(
        const float* __restrict__ pre, const float* __restrict__ W_att,
        const float* __restrict__ W_g, const float* __restrict__ b_g,
        const float* __restrict__ mask) {
    __shared__ float cs[CCH * 64];        // [c][tloc]
    __shared__ float ws[CCH * 132];       // [c][aloc], padded row 132
    __shared__ float dzs[AD];
    __shared__ float wgs[AD];

    const int tid = threadIdx.x;
    const int tx = tid & 31;
    const int ty = tid >> 5;
    const int t0 = blockIdx.x * 64;

    for (int i = tid; i < CCH * 64; i += 256) {
        int c = i >> 6, tl = i & 63;
        cs[i] = g_conv[c * T_LEN + t0 + tl];
    }
    for (int i = tid; i < AD; i += 256) { dzs[i] = g_dz[i]; wgs[i] = W_g[i]; }
    __syncthreads();

    float esum[8];
    #pragma unroll
    for (int i = 0; i < 8; i++) esum[i] = 0.f;

    const float4* cs4 = (const float4*)cs;

    for (int chunk = 0; chunk < 4; chunk++) {
        // stage W_att chunk into shared, transposed to [c][aloc]
        for (int i = tid; i < 128 * 32; i += 256) {
            int al = i >> 5, c = i & 31;
            ws[c * 132 + al] = W_att[(chunk * 128 + al) * 32 + c];
        }
        __syncthreads();

        const float4* ws4 = (const float4*)ws;
        float4 proj[8];
        #pragma unroll
        for (int i = 0; i < 8; i++) proj[i] = make_float4(0.f, 0.f, 0.f, 0.f);

        #pragma unroll
        for (int c = 0; c < 32; c++) {
            float4 w4 = ws4[c * 33 + tx];
            float4 ca = cs4[c * 16 + ty * 2];
            float4 cb2 = cs4[c * 16 + ty * 2 + 1];
            #define PACC(P, s) P.x += (s)*w4.x; P.y += (s)*w4.y; P.z += (s)*w4.z; P.w += (s)*w4.w;
            PACC(proj[0], ca.x)  PACC(proj[1], ca.y)  PACC(proj[2], ca.z)  PACC(proj[3], ca.w)
            PACC(proj[4], cb2.x) PACC(proj[5], cb2.y) PACC(proj[6], cb2.z) PACC(proj[7], cb2.w)
            #undef PACC
        }

        float4 d4 = ((const float4*)dzs)[chunk * 32 + tx];
        float4 g4 = ((const float4*)wgs)[chunk * 32 + tx];
        #pragma unroll
        for (int i = 0; i < 8; i++) {
            int t = t0 + ty * 8 + i;
            const float4 pr = __ldg((const float4*)(pre + (size_t)t * AD + chunk * 128 + tx * 4));
            float x0 = pr.x + d4.x + proj[i].x;
            float x1 = pr.y + d4.y + proj[i].y;
            float x2 = pr.z + d4.z + proj[i].z;
            float x3 = pr.w + d4.w + proj[i].w;
            esum[i] += g4.x * tanh_f(x0) + g4.y * tanh_f(x1)
                     + g4.z * tanh_f(x2) + g4.w * tanh_f(x3);
        }
        __syncthreads();
    }

    const float bg = __ldg(b_g);
    #pragma unroll
    for (int i = 0; i < 8; i++) {
        float v = esum[i];
        #pragma unroll
        for (int o = 16; o; o >>= 1) v += __shfl_xor_sync(0xffffffffu, v, o);
        if (tx == 0) {
            int t = t0 + ty * 8 + i;
            g_e[t] = v + bg + mask[t];
        }
    }
}

// ---------------- k_redmax: emax over e ----------------
__global__ void k_redmax() {
    __shared__ float sm[1024];
    float m = -1e30f;
    for (int i = threadIdx.x; i < T_LEN; i += 1024) m = fmaxf(m, g_e[i]);
    sm[threadIdx.x] = m;
    __syncthreads();
    for (int s = 512; s; s >>= 1) {
        if (threadIdx.x < s) sm[threadIdx.x] = fmaxf(sm[threadIdx.x], sm[threadIdx.x + s]);
        __syncthreads();
    }
    if (threadIdx.x == 0) g_emax = sm[0];
}

// ---------------- k_exp: wexp, q = (ap[t]+ap[t-1])*wexp, partial S ---------
__global__ void k_exp(const float* __restrict__ ap) {
    int t = blockIdx.x * 256 + threadIdx.x;
    float emax = g_emax;
    float wexp = __expf(2.0f * (g_e[t] - emax));
    float ap2 = ap[t] + (t > 0 ? ap[t - 1] : 0.f);
    g_q[t] = ap2 * wexp;
    __shared__ float sm[256];
    sm[threadIdx.x] = wexp;
    __syncthreads();
    for (int s = 128; s; s >>= 1) {
        if (threadIdx.x < s) sm[threadIdx.x] += sm[threadIdx.x + s];
        __syncthreads();
    }
    if (threadIdx.x == 0) g_partS[blockIdx.x] = sm[0];
}

// ---------------- k_p: p = max(q/S, 1e-6), partial sum2 --------------------
__global__ void k_p() {
    __shared__ float sm[256];
    sm[threadIdx.x] = (threadIdx.x < NBRED) ? g_partS[threadIdx.x] : 0.f;
    __syncthreads();
    for (int s = 128; s; s >>= 1) {
        if (threadIdx.x < s) sm[threadIdx.x] += sm[threadIdx.x + s];
        __syncthreads();
    }
    float S = sm[0];
    __syncthreads();
    int t = blockIdx.x * 256 + threadIdx.x;
    float p = fmaxf(__fdividef(g_q[t], S), 1e-6f);
    g_p[t] = p;
    sm[threadIdx.x] = p;
    __syncthreads();
    for (int s = 128; s; s >>= 1) {
        if (threadIdx.x < s) sm[threadIdx.x] += sm[threadIdx.x + s];
        __syncthreads();
    }
    if (threadIdx.x == 0) g_part2[blockIdx.x] = sm[0];
}

// ---------------- k_final: w = p/sum2 (to out), partial c ------------------
__global__ void k_final(const float* __restrict__ enc_h, float* __restrict__ w_out) {
    __shared__ float sm[256];
    sm[threadIdx.x] = (threadIdx.x < NBRED) ? g_part2[threadIdx.x] : 0.f;
    __syncthreads();
    for (int s = 128; s; s >>= 1) {
        if (threadIdx.x < s) sm[threadIdx.x] += sm[threadIdx.x + s];
        __syncthreads();
    }
    float inv = 1.0f / sm[0];
    int t0 = blockIdx.x * 256;
    int tw = t0 + threadIdx.x;
    w_out[tw] = g_p[tw] * inv;

    float2 acc = make_float2(0.f, 0.f);
    const float2* eh = (const float2*)enc_h;
    for (int t = t0; t < t0 + 256; t++) {
        float w = g_p[t] * inv;
        float2 v = __ldg(eh + (size_t)t * (EP / 2) + threadIdx.x);
        acc.x += v.x * w;
        acc.y += v.y * w;
    }
    g_cpart[blockIdx.x * EP + threadIdx.x * 2]     = acc.x;
    g_cpart[blockIdx.x * EP + threadIdx.x * 2 + 1] = acc.y;
}

// ---------------- k_cred: c[j] = sum_b cpart[b][j] -------------------------
__global__ void k_cred(float* __restrict__ c_out) {
    int j = threadIdx.x;   // 512 threads
    float s = 0.f;
    #pragma unroll 4
    for (int b = 0; b < NBRED; b++) s += g_cpart[b * EP + j];
    c_out[j] = s;
}

// ---------------- launch ----------------
extern "C" void kernel_launch(void* const* d_in, const int* in_sizes, int n_in,
                              void* d_out, int out_size) {
    const float* dec_z   = (const float*)d_in[0];
    const float* att_prev= (const float*)d_in[1];
    const float* pre     = (const float*)d_in[2];
    const float* enc_h   = (const float*)d_in[3];
    const float* mask    = (const float*)d_in[4];
    const float* conv_w  = (const float*)d_in[5];
    const float* conv_b  = (const float*)d_in[6];
    const float* W_att   = (const float*)d_in[7];
    const float* W_dec   = (const float*)d_in[8];
    const float* W_g     = (const float*)d_in[9];
    const float* b_g     = (const float*)d_in[10];
    float* out = (float*)d_out;            // [0:512) = c, [512:512+T) = w

    k_dz<<<64, 256>>>(dec_z, W_dec);
    k_conv<<<4096, 256>>>(att_prev, conv_w, conv_b);
    k_e<<<T_LEN / 64, 256>>>(pre, W_att, W_g, b_g, mask);
    k_redmax<<<1, 1024>>>();
    k_exp<<<NBRED, 256>>>(att_prev);
    k_p<<<NBRED, 256>>>();
    k_final<<<NBRED, 256>>>(enc_h, out + 512);
    k_cred<<<1, 512>>>(out);
}

// round 2
// speedup vs baseline: 1.1545x; 1.1545x over previous
#include <cuda_runtime.h>
#include <math.h>

#define T_LEN 32768
#define AD 512
#define CCH 32
#define KF 31
#define DU 1024
#define EP 512

// ---------------- scratch (device globals; no allocation) ----------------
__device__ float g_conv[CCH * T_LEN];     // [c][t]
__device__ float g_dz[AD];
__device__ float g_e[T_LEN];
__device__ float g_bmax[512];
__device__ float g_q[T_LEN];
__device__ float g_p[T_LEN];
__device__ float g_partS[128];
__device__ float g_part2[128];
__device__ float g_cpart[128 * EP];

__device__ __forceinline__ float tanh_f(float x) {
    float e = __expf(2.0f * x);
    return 1.0f - __fdividef(2.0f, e + 1.0f);
}

__device__ __forceinline__ unsigned long long pk2(float a, float b) {
    unsigned long long r;
    asm("mov.b64 %0, {%1,%2};" : "=l"(r) : "f"(a), "f"(b));
    return r;
}
__device__ __forceinline__ float2 upk2(unsigned long long v) {
    float2 r;
    asm("mov.b64 {%0,%1}, %2;" : "=f"(r.x), "=f"(r.y) : "l"(v));
    return r;
}
__device__ __forceinline__ void fma2(unsigned long long& d, unsigned long long a,
                                     unsigned long long b) {
    asm("fma.rn.f32x2 %0, %1, %2, %0;" : "+l"(d) : "l"(a), "l"(b));
}

// ---------------- k_misc: conv (blocks 0..4095) + dz GEMV (4096..4159) -----
__global__ void k_misc(const float* __restrict__ ap, const float* __restrict__ cw,
                       const float* __restrict__ cb, const float* __restrict__ dec_z,
                       const float* __restrict__ W_dec) {
    if (blockIdx.x < 4096) {
        int b = blockIdx.x;
        int c = b >> 7;
        int t = ((b & 127) << 8) + threadIdx.x;
        float acc = __ldg(cb + c);
        const float* w = cw + c * KF;
        #pragma unroll
        for (int f = 0; f < KF; f++) {
            int idx = t - 15 + f;
            float a = (idx >= 0 && idx < T_LEN) ? __ldg(ap + idx) : 0.f;
            acc += a * __ldg(w + f);
        }
        g_conv[c * T_LEN + t] = acc;
    } else {
        int warp = (blockIdx.x - 4096) * 8 + (threadIdx.x >> 5);
        int lane = threadIdx.x & 31;
        if (warp >= AD) return;
        const float* row = W_dec + warp * DU;
        float acc = 0.f;
        #pragma unroll 4
        for (int k = lane; k < DU; k += 32) acc += row[k] * dec_z[k];
        #pragma unroll
        for (int o = 16; o; o >>= 1) acc += __shfl_xor_sync(0xffffffffu, acc, o);
        if (lane == 0) g_dz[warp] = acc;
    }
}

// ---------------- k_e: fused proj-GEMM(f32x2) + tanh + W_g dot -> e[t] -----
// block = 64 t x 512 a (4 chunks of 128a). 256 threads; thread tile 8t x 4a.
// t-pairs packed into b64 so conv operands load pre-packed from shared.
__global__ __launch_bounds__(256, 2) void k_e(
        const float* __restrict__ pre, const float* __restrict__ W_att,
        const float* __restrict__ W_g, const float* __restrict__ b_g,
        const float* __restrict__ mask) {
    __shared__ float cs[CCH * 64];        // [c][tloc]
    __shared__ float ws[CCH * 132];       // [c][aloc], padded
    __shared__ float dzs[AD];
    __shared__ float wgs[AD];
    __shared__ float wmax[8];

    const int tid = threadIdx.x;
    const int tx = tid & 31;
    const int ty = tid >> 5;
    const int t0 = blockIdx.x * 64;

    for (int i = tid; i < CCH * 64; i += 256) {
        int c = i >> 6, tl = i & 63;
        cs[i] = g_conv[c * T_LEN + t0 + tl];
    }
    for (int i = tid; i < AD; i += 256) { dzs[i] = g_dz[i]; wgs[i] = W_g[i]; }
    __syncthreads();

    float esum[8];
    #pragma unroll
    for (int i = 0; i < 8; i++) esum[i] = 0.f;

    for (int chunk = 0; chunk < 4; chunk++) {
        for (int i = tid; i < 128 * 32; i += 256) {
            int al = i >> 5, c = i & 31;
            ws[c * 132 + al] = W_att[(chunk * 128 + al) * 32 + c];
        }
        __syncthreads();

        const float4* ws4 = (const float4*)ws;
        unsigned long long acc[16];       // [t-pair 0..3][a 0..3]
        #pragma unroll
        for (int i = 0; i < 16; i++) acc[i] = 0ull;

        #pragma unroll
        for (int c = 0; c < 32; c++) {
            const ulonglong2 A = *(const ulonglong2*)(cs + c * 64 + ty * 8);
            const ulonglong2 B = *(const ulonglong2*)(cs + c * 64 + ty * 8 + 4);
            const float4 w4 = ws4[c * 33 + tx];
            unsigned long long w0 = pk2(w4.x, w4.x), w1 = pk2(w4.y, w4.y);
            unsigned long long w2 = pk2(w4.z, w4.z), w3 = pk2(w4.w, w4.w);
            fma2(acc[0],  A.x, w0); fma2(acc[1],  A.x, w1);
            fma2(acc[2],  A.x, w2); fma2(acc[3],  A.x, w3);
            fma2(acc[4],  A.y, w0); fma2(acc[5],  A.y, w1);
            fma2(acc[6],  A.y, w2); fma2(acc[7],  A.y, w3);
            fma2(acc[8],  B.x, w0); fma2(acc[9],  B.x, w1);
            fma2(acc[10], B.x, w2); fma2(acc[11], B.x, w3);
            fma2(acc[12], B.y, w0); fma2(acc[13], B.y, w1);
            fma2(acc[14], B.y, w2); fma2(acc[15], B.y, w3);
        }

        const float4 d4 = ((const float4*)dzs)[chunk * 32 + tx];
        const float4 g4 = ((const float4*)wgs)[chunk * 32 + tx];
        #pragma unroll
        for (int p = 0; p < 4; p++) {
            float2 p0 = upk2(acc[p * 4 + 0]);
            float2 p1 = upk2(acc[p * 4 + 1]);
            float2 p2 = upk2(acc[p * 4 + 2]);
            float2 p3 = upk2(acc[p * 4 + 3]);
            #pragma unroll
            for (int h = 0; h < 2; h++) {
                int i = p * 2 + h;
                int t = t0 + ty * 8 + i;
                const float4 pr = __ldg((const float4*)(pre + (size_t)t * AD
                                                        + chunk * 128 + tx * 4));
                float q0 = h ? p0.y : p0.x;
                float q1 = h ? p1.y : p1.x;
                float q2 = h ? p2.y : p2.x;
                float q3 = h ? p3.y : p3.x;
                esum[i] += g4.x * tanh_f(pr.x + d4.x + q0)
                         + g4.y * tanh_f(pr.y + d4.y + q1)
                         + g4.z * tanh_f(pr.z + d4.z + q2)
                         + g4.w * tanh_f(pr.w + d4.w + q3);
            }
        }
        __syncthreads();
    }

    const float bg = __ldg(b_g);
    float m = -1e30f;
    #pragma unroll
    for (int i = 0; i < 8; i++) {
        float v = esum[i];
        #pragma unroll
        for (int o = 16; o; o >>= 1) v += __shfl_xor_sync(0xffffffffu, v, o);
        if (tx == 0) {
            int t = t0 + ty * 8 + i;
            float e = v + bg + mask[t];
            g_e[t] = e;
            m = fmaxf(m, e);
        }
    }
    if (tx == 0) wmax[ty] = m;
    __syncthreads();
    if (tid == 0) {
        float bm = wmax[0];
        #pragma unroll
        for (int i = 1; i < 8; i++) bm = fmaxf(bm, wmax[i]);
        g_bmax[blockIdx.x] = bm;
    }
}

// ---------------- k_exp: reduce bmax, wexp, q, partial S -------------------
__global__ void k_exp(const float* __restrict__ ap) {
    __shared__ float sm[256];
    float mm = fmaxf(g_bmax[threadIdx.x], g_bmax[threadIdx.x + 256]);
    sm[threadIdx.x] = mm;
    __syncthreads();
    for (int s = 128; s; s >>= 1) {
        if (threadIdx.x < s) sm[threadIdx.x] = fmaxf(sm[threadIdx.x], sm[threadIdx.x + s]);
        __syncthreads();
    }
    const float emax = sm[0];
    __syncthreads();

    int t = blockIdx.x * 256 + threadIdx.x;
    float wexp = __expf(2.0f * (g_e[t] - emax));
    float ap2 = ap[t] + (t > 0 ? ap[t - 1] : 0.f);
    g_q[t] = ap2 * wexp;
    sm[threadIdx.x] = wexp;
    __syncthreads();
    for (int s = 128; s; s >>= 1) {
        if (threadIdx.x < s) sm[threadIdx.x] += sm[threadIdx.x + s];
        __syncthreads();
    }
    if (threadIdx.x == 0) g_partS[blockIdx.x] = sm[0];
}

// ---------------- k_mid: S, p, partial sum2, partial c = enc_h . p ---------
// 128 blocks x 256 t each. Two col-groups of 128 threads, each covers 128 t.
__global__ __launch_bounds__(256, 4) void k_mid(const float* __restrict__ enc_h) {
    __shared__ float sm[256];
    __shared__ float psm[256];
    __shared__ float csum[EP];

    const int tid = threadIdx.x;
    const int t0 = blockIdx.x * 256;

    sm[tid] = (tid < 128) ? g_partS[tid] : 0.f;
    __syncthreads();
    for (int s = 128; s; s >>= 1) {
        if (tid < s) sm[tid] += sm[tid + s];
        __syncthreads();
    }
    const float invS = __fdividef(1.0f, sm[0]);
    __syncthreads();

    float p = fmaxf(g_q[t0 + tid] * invS, 1e-6f);
    g_p[t0 + tid] = p;
    psm[tid] = p;
    sm[tid] = p;
    __syncthreads();
    for (int s = 128; s; s >>= 1) {
        if (tid < s) sm[tid] += sm[tid + s];
        __syncthreads();
    }
    if (tid == 0) g_part2[blockIdx.x] = sm[0];

    // enc_h . p : group g handles t-subrange [g*128, g*128+128)
    const int grp = tid >> 7;
    const int cw = tid & 127;            // cols cw*4 .. cw*4+3
    float4 acc = make_float4(0.f, 0.f, 0.f, 0.f);
    const float4* eh = (const float4*)(enc_h + (size_t)(t0 + grp * 128) * EP) + cw;
    #pragma unroll 4
    for (int j = 0; j < 128; j++) {
        float w = psm[grp * 128 + j];
        float4 v = __ldg(eh + j * (EP / 4));
        acc.x += v.x * w; acc.y += v.y * w; acc.z += v.z * w; acc.w += v.w * w;
    }
    if (grp == 0) {
        csum[cw * 4 + 0] = acc.x; csum[cw * 4 + 1] = acc.y;
        csum[cw * 4 + 2] = acc.z; csum[cw * 4 + 3] = acc.w;
    }
    __syncthreads();
    if (grp == 1) {
        g_cpart[blockIdx.x * EP + cw * 4 + 0] = csum[cw * 4 + 0] + acc.x;
        g_cpart[blockIdx.x * EP + cw * 4 + 1] = csum[cw * 4 + 1] + acc.y;
        g_cpart[blockIdx.x * EP + cw * 4 + 2] = csum[cw * 4 + 2] + acc.z;
        g_cpart[blockIdx.x * EP + cw * 4 + 3] = csum[cw * 4 + 3] + acc.w;
    }
}

// ---------------- k_fin: w = p/sum2 ; c = (sum_b cpart)/sum2 ---------------
__global__ void k_fin(float* __restrict__ out) {
    __shared__ float sm[256];
    const int tid = threadIdx.x;
    sm[tid] = (tid < 128) ? g_part2[tid] : 0.f;
    __syncthreads();
    for (int s = 128; s; s >>= 1) {
        if (tid < s) sm[tid] += sm[tid + s];
        __syncthreads();
    }
    const float inv = __fdividef(1.0f, sm[0]);

    if (blockIdx.x < 128) {
        int t = blockIdx.x * 256 + tid;
        out[512 + t] = g_p[t] * inv;           // w
    } else {
        int b = blockIdx.x - 128;              // 0..3
        if (tid < 128) {
            int col = b * 128 + tid;
            float s = 0.f;
            #pragma unroll 4
            for (int k = 0; k < 128; k++) s += g_cpart[k * EP + col];
            out[col] = s * inv;                // c
        }
    }
}

// ---------------- launch ----------------
extern "C" void kernel_launch(void* const* d_in, const int* in_sizes, int n_in,
                              void* d_out, int out_size) {
    const float* dec_z    = (const float*)d_in[0];
    const float* att_prev = (const float*)d_in[1];
    const float* pre      = (const float*)d_in[2];
    const float* enc_h    = (const float*)d_in[3];
    const float* mask     = (const float*)d_in[4];
    const float* conv_w   = (const float*)d_in[5];
    const float* conv_b   = (const float*)d_in[6];
    const float* W_att    = (const float*)d_in[7];
    const float* W_dec    = (const float*)d_in[8];
    const float* W_g      = (const float*)d_in[9];
    const float* b_g      = (const float*)d_in[10];
    float* out = (float*)d_out;   // [0:512) = c, [512:512+T) = w

    k_misc<<<4160, 256>>>(att_prev, conv_w, conv_b, dec_z, W_dec);
    k_e<<<T_LEN / 64, 256>>>(pre, W_att, W_g, b_g, mask);
    k_exp<<<128, 256>>>(att_prev);
    k_mid<<<128, 256>>>(enc_h);
    k_fin<<<132, 256>>>(out);
}

// round 3
// speedup vs baseline: 1.3983x; 1.2112x over previous
#include <cuda_runtime.h>
#include <math.h>

#define T_LEN 32768
#define AD 512
#define CCH 32
#define KF 31
#define DU 1024
#define EP 512
#define NBMID 1024

// ---------------- scratch (device globals; no allocation) ----------------
__device__ float g_conv[CCH * T_LEN];
__device__ float g_dz[AD];
__device__ float g_e[T_LEN];
__device__ float g_bmax[512];
__device__ float g_q[T_LEN];
__device__ float g_p[T_LEN];
__device__ float g_partS[128];
__device__ float g_part2[NBMID];
__device__ float g_cpart[NBMID * EP];

__device__ __forceinline__ float tanh_f(float x) {
    float e = __expf(2.0f * x);
    return 1.0f - __fdividef(2.0f, e + 1.0f);
}
__device__ __forceinline__ unsigned long long pk2(float a, float b) {
    unsigned long long r;
    asm("mov.b64 %0, {%1,%2};" : "=l"(r) : "f"(a), "f"(b));
    return r;
}
__device__ __forceinline__ float2 upk2(unsigned long long v) {
    float2 r;
    asm("mov.b64 {%0,%1}, %2;" : "=f"(r.x), "=f"(r.y) : "l"(v));
    return r;
}
__device__ __forceinline__ void fma2(unsigned long long& d, unsigned long long a,
                                     unsigned long long b) {
    asm("fma.rn.f32x2 %0, %1, %2, %0;" : "+l"(d) : "l"(a), "l"(b));
}

// ------- k_misc: conv (blocks 0..127, 256 t each) + dz GEMV (128..191) -----
__global__ __launch_bounds__(256) void k_misc(
        const float* __restrict__ ap, const float* __restrict__ cw,
        const float* __restrict__ cb, const float* __restrict__ dec_z,
        const float* __restrict__ W_dec) {
    if (blockIdx.x < 128) {
        __shared__ float apt[286];
        __shared__ float wsm[CCH * KF];
        __shared__ float wb[CCH];
        const int tid = threadIdx.x;
        const int t0 = blockIdx.x * 256;
        for (int i = tid; i < 286; i += 256) {
            int g = t0 - 15 + i;
            apt[i] = (g >= 0 && g < T_LEN) ? ap[g] : 0.f;
        }
        for (int i = tid; i < CCH * KF; i += 256) wsm[i] = cw[i];
        if (tid < CCH) wb[tid] = cb[tid];
        __syncthreads();

        float win[KF];
        #pragma unroll
        for (int f = 0; f < KF; f++) win[f] = apt[tid + f];

        #pragma unroll 2
        for (int c = 0; c < CCH; c++) {
            float acc = wb[c];
            #pragma unroll
            for (int f = 0; f < KF; f++) acc += win[f] * wsm[c * KF + f];
            g_conv[c * T_LEN + t0 + tid] = acc;
        }
    } else {
        int warp = (blockIdx.x - 128) * 8 + (threadIdx.x >> 5);
        int lane = threadIdx.x & 31;
        const float* row = W_dec + warp * DU;
        float acc = 0.f;
        #pragma unroll 4
        for (int k = lane; k < DU; k += 32) acc += row[k] * dec_z[k];
        #pragma unroll
        for (int o = 16; o; o >>= 1) acc += __shfl_xor_sync(0xffffffffu, acc, o);
        if (lane == 0) g_dz[warp] = acc;
    }
}

// ---------------- k_e: fused proj-GEMM(f32x2) + tanh + W_g dot -> e[t] -----
// block = 64 t x 512 a. 256 threads; thread tile 8t x 4a. W_att staged once.
__global__ __launch_bounds__(256, 2) void k_e(
        const float* __restrict__ pre, const float* __restrict__ W_att,
        const float* __restrict__ W_g, const float* __restrict__ b_g,
        const float* __restrict__ mask) {
    extern __shared__ float dyn[];
    float* cs  = dyn;                  // [c][tloc]  32*64
    float* ws  = dyn + 2048;           // [c][a 520] 32*520
    float* dzs = ws + 32 * 520;        // 512
    float* wgs = dzs + 512;            // 512
    __shared__ float wmax[8];

    const int tid = threadIdx.x;
    const int tx = tid & 31;
    const int ty = tid >> 5;
    const int t0 = blockIdx.x * 64;

    for (int i = tid; i < CCH * 64; i += 256) {
        int c = i >> 6, tl = i & 63;
        cs[i] = g_conv[c * T_LEN + t0 + tl];
    }
    for (int i = tid; i < AD * CCH; i += 256) {
        int al = i >> 5, c = i & 31;
        ws[c * 520 + al] = W_att[i];
    }
    for (int i = tid; i < AD; i += 256) { dzs[i] = g_dz[i]; wgs[i] = W_g[i]; }
    __syncthreads();

    float esum[8];
    #pragma unroll
    for (int i = 0; i < 8; i++) esum[i] = 0.f;

    const float4* ws4 = (const float4*)ws;   // row stride 130 float4

    #pragma unroll 1
    for (int chunk = 0; chunk < 4; chunk++) {
        unsigned long long acc[16];
        #pragma unroll
        for (int i = 0; i < 16; i++) acc[i] = 0ull;

        #pragma unroll
        for (int c = 0; c < 32; c++) {
            const ulonglong2 A = *(const ulonglong2*)(cs + c * 64 + ty * 8);
            const ulonglong2 B = *(const ulonglong2*)(cs + c * 64 + ty * 8 + 4);
            const float4 w4 = ws4[c * 130 + chunk * 32 + tx];
            unsigned long long w0 = pk2(w4.x, w4.x), w1 = pk2(w4.y, w4.y);
            unsigned long long w2 = pk2(w4.z, w4.z), w3 = pk2(w4.w, w4.w);
            fma2(acc[0],  A.x, w0); fma2(acc[1],  A.x, w1);
            fma2(acc[2],  A.x, w2); fma2(acc[3],  A.x, w3);
            fma2(acc[4],  A.y, w0); fma2(acc[5],  A.y, w1);
            fma2(acc[6],  A.y, w2); fma2(acc[7],  A.y, w3);
            fma2(acc[8],  B.x, w0); fma2(acc[9],  B.x, w1);
            fma2(acc[10], B.x, w2); fma2(acc[11], B.x, w3);
            fma2(acc[12], B.y, w0); fma2(acc[13], B.y, w1);
            fma2(acc[14], B.y, w2); fma2(acc[15], B.y, w3);
        }

        const float4 d4 = ((const float4*)dzs)[chunk * 32 + tx];
        const float4 g4 = ((const float4*)wgs)[chunk * 32 + tx];
        #pragma unroll
        for (int p = 0; p < 4; p++) {
            float2 p0 = upk2(acc[p * 4 + 0]);
            float2 p1 = upk2(acc[p * 4 + 1]);
            float2 p2 = upk2(acc[p * 4 + 2]);
            float2 p3 = upk2(acc[p * 4 + 3]);
            #pragma unroll
            for (int h = 0; h < 2; h++) {
                int i = p * 2 + h;
                int t = t0 + ty * 8 + i;
                const float4 pr = __ldg((const float4*)(pre + (size_t)t * AD
                                                        + chunk * 128 + tx * 4));
                float q0 = h ? p0.y : p0.x;
                float q1 = h ? p1.y : p1.x;
                float q2 = h ? p2.y : p2.x;
                float q3 = h ? p3.y : p3.x;
                esum[i] += g4.x * tanh_f(pr.x + d4.x + q0)
                         + g4.y * tanh_f(pr.y + d4.y + q1)
                         + g4.z * tanh_f(pr.z + d4.z + q2)
                         + g4.w * tanh_f(pr.w + d4.w + q3);
            }
        }
    }

    const float bg = __ldg(b_g);
    float m = -1e30f;
    #pragma unroll
    for (int i = 0; i < 8; i++) {
        float v = esum[i];
        #pragma unroll
        for (int o = 16; o; o >>= 1) v += __shfl_xor_sync(0xffffffffu, v, o);
        if (tx == 0) {
            int t = t0 + ty * 8 + i;
            float e = v + bg + mask[t];
            g_e[t] = e;
            m = fmaxf(m, e);
        }
    }
    if (tx == 0) wmax[ty] = m;
    __syncthreads();
    if (tid == 0) {
        float bm = wmax[0];
        #pragma unroll
        for (int i = 1; i < 8; i++) bm = fmaxf(bm, wmax[i]);
        g_bmax[blockIdx.x] = bm;
    }
}

// ---------------- k_exp: reduce bmax, wexp, q, partial S -------------------
__global__ void k_exp(const float* __restrict__ ap) {
    __shared__ float sm[256];
    float mm = fmaxf(g_bmax[threadIdx.x], g_bmax[threadIdx.x + 256]);
    sm[threadIdx.x] = mm;
    __syncthreads();
    for (int s = 128; s; s >>= 1) {
        if (threadIdx.x < s) sm[threadIdx.x] = fmaxf(sm[threadIdx.x], sm[threadIdx.x + s]);
        __syncthreads();
    }
    const float emax = sm[0];
    __syncthreads();

    int t = blockIdx.x * 256 + threadIdx.x;
    float wexp = __expf(2.0f * (g_e[t] - emax));
    float ap2 = ap[t] + (t > 0 ? ap[t - 1] : 0.f);
    g_q[t] = ap2 * wexp;
    sm[threadIdx.x] = wexp;
    __syncthreads();
    for (int s = 128; s; s >>= 1) {
        if (threadIdx.x < s) sm[threadIdx.x] += sm[threadIdx.x + s];
        __syncthreads();
    }
    if (threadIdx.x == 0) g_partS[blockIdx.x] = sm[0];
}

// ---------------- k_mid: S, p, partial sum2, partial c = enc_h . p ---------
// 1024 blocks x 256 thr; each block covers 32 t. 2 col-groups x 16 t each.
__global__ __launch_bounds__(256) void k_mid(const float* __restrict__ enc_h) {
    __shared__ float sm[128];
    __shared__ float psm[32];
    __shared__ float csum[EP];

    const int tid = threadIdx.x;
    const int t0 = blockIdx.x * 32;

    if (tid < 128) sm[tid] = g_partS[tid];
    __syncthreads();
    for (int s = 64; s; s >>= 1) {
        if (tid < s) sm[tid] += sm[tid + s];
        __syncthreads();
    }
    const float invS = __fdividef(1.0f, sm[0]);
    __syncthreads();

    if (tid < 32) {
        float p = fmaxf(g_q[t0 + tid] * invS, 1e-6f);
        g_p[t0 + tid] = p;
        psm[tid] = p;
        float v = p;
        #pragma unroll
        for (int o = 16; o; o >>= 1) v += __shfl_xor_sync(0xffffffffu, v, o);
        if (tid == 0) g_part2[blockIdx.x] = v;
    }
    __syncthreads();

    // enc_h . p : group g handles t-subrange [t0+g*16, +16)
    const int grp = tid >> 7;
    const int cw = tid & 127;            // cols cw*4 .. cw*4+3
    float4 acc = make_float4(0.f, 0.f, 0.f, 0.f);
    const float4* eh = (const float4*)(enc_h + (size_t)(t0 + grp * 16) * EP) + cw;
    #pragma unroll 8
    for (int j = 0; j < 16; j++) {
        float w = psm[grp * 16 + j];
        float4 v = __ldg(eh + j * (EP / 4));
        acc.x += v.x * w; acc.y += v.y * w; acc.z += v.z * w; acc.w += v.w * w;
    }
    if (grp == 0) {
        csum[cw * 4 + 0] = acc.x; csum[cw * 4 + 1] = acc.y;
        csum[cw * 4 + 2] = acc.z; csum[cw * 4 + 3] = acc.w;
    }
    __syncthreads();
    if (grp == 1) {
        g_cpart[blockIdx.x * EP + cw * 4 + 0] = csum[cw * 4 + 0] + acc.x;
        g_cpart[blockIdx.x * EP + cw * 4 + 1] = csum[cw * 4 + 1] + acc.y;
        g_cpart[blockIdx.x * EP + cw * 4 + 2] = csum[cw * 4 + 2] + acc.z;
        g_cpart[blockIdx.x * EP + cw * 4 + 3] = csum[cw * 4 + 3] + acc.w;
    }
}

// ---------------- k_fin: w = p/sum2 ; c = (sum_b cpart)/sum2 ---------------
// 512 threads. blocks 0..63: w (512 t each). blocks 64..67: c (128 cols each).
__global__ __launch_bounds__(512) void k_fin(float* __restrict__ out) {
    __shared__ float sm[512];
    __shared__ float cacc[512];
    const int tid = threadIdx.x;
    sm[tid] = g_part2[tid] + g_part2[tid + 512];
    __syncthreads();
    for (int s = 256; s; s >>= 1) {
        if (tid < s) sm[tid] += sm[tid + s];
        __syncthreads();
    }
    const float inv = __fdividef(1.0f, sm[0]);

    if (blockIdx.x < 64) {
        int t = blockIdx.x * 512 + tid;
        out[512 + t] = g_p[t] * inv;           // w
    } else {
        int cb = blockIdx.x - 64;              // 0..3
        int col = cb * 128 + (tid & 127);
        int seg = tid >> 7;                    // 0..3, each sums 256 blocks
        float s = 0.f;
        #pragma unroll 8
        for (int k = seg * 256; k < seg * 256 + 256; k++)
            s += g_cpart[k * EP + col];
        cacc[tid] = s;
        __syncthreads();
        if (seg == 0)
            out[col] = (cacc[tid] + cacc[tid + 128] + cacc[tid + 256]
                        + cacc[tid + 384]) * inv;   // c
    }
}

// ---------------- launch ----------------
extern "C" void kernel_launch(void* const* d_in, const int* in_sizes, int n_in,
                              void* d_out, int out_size) {
    const float* dec_z    = (const float*)d_in[0];
    const float* att_prev = (const float*)d_in[1];
    const float* pre      = (const float*)d_in[2];
    const float* enc_h    = (const float*)d_in[3];
    const float* mask     = (const float*)d_in[4];
    const float* conv_w   = (const float*)d_in[5];
    const float* conv_b   = (const float*)d_in[6];
    const float* W_att    = (const float*)d_in[7];
    const float* W_dec    = (const float*)d_in[8];
    const float* W_g      = (const float*)d_in[9];
    const float* b_g      = (const float*)d_in[10];
    float* out = (float*)d_out;   // [0:512) = c, [512:512+T) = w

    const int ke_smem = (2048 + 32 * 520 + 1024) * 4;   // 78848 B
    cudaFuncSetAttribute(k_e, cudaFuncAttributeMaxDynamicSharedMemorySize, ke_smem);

    k_misc<<<192, 256>>>(att_prev, conv_w, conv_b, dec_z, W_dec);
    k_e<<<T_LEN / 64, 256, ke_smem>>>(pre, W_att, W_g, b_g, mask);
    k_exp<<<128, 256>>>(att_prev);
    k_mid<<<NBMID, 256>>>(enc_h);
    k_fin<<<68, 512>>>(out);
}